// round 2
// baseline (speedup 1.0000x reference)
#include <cuda_runtime.h>
#include <cuda_bf16.h>
#include <cstdint>

#define GRID_DIM 201

// Self-resetting accumulator state (zero-initialized at module load; the
// finishing block resets them each launch, so graph replays stay correct).
__device__ float        g_partial = 0.0f;
__device__ unsigned int g_count   = 0;

__device__ __forceinline__ float sample_w(const float* __restrict__ wg,
                                          float px, float py) {
    // floor((p*180-90)/0.9)+100 == floor(p*200); same for lon with 1.8.
    int xi = __float2int_rd(px * 200.0f);
    int yi = __float2int_rd(py * 200.0f);
    xi = min(max(xi, 0), GRID_DIM - 1);
    yi = min(max(yi, 0), GRID_DIM - 1);
    return __ldg(&wg[xi * GRID_DIM + yi]);
}

__device__ __forceinline__ float proc4(float4 p, float4 l,
                                       const float* __restrict__ wg) {
    float e0 = fabsf(p.x - l.x) + fabsf(p.y - l.y);   // sample 0 abs-err sum
    float e1 = fabsf(p.z - l.z) + fabsf(p.w - l.w);   // sample 1
    float w0 = sample_w(wg, p.x, p.y);
    float w1 = sample_w(wg, p.z, p.w);
    // err * (1 + alpha - alpha*w)
    return fmaf(e0, fmaf(-0.1f, w0, 1.1f), e1 * fmaf(-0.1f, w1, 1.1f));
}

__global__ void __launch_bounds__(256)
wmse_kernel(const float* __restrict__ pred,
            const float* __restrict__ lab,
            const float* __restrict__ wg,
            float* __restrict__ out,
            int nvec,            // float4 chunks (2 samples each)
            float inv_count)     // 1/(B*2)
{
    const float4* __restrict__ p4 = reinterpret_cast<const float4*>(pred);
    const float4* __restrict__ l4 = reinterpret_cast<const float4*>(lab);

    float acc = 0.0f;
    const int stride = gridDim.x * blockDim.x;
    int i = blockIdx.x * blockDim.x + threadIdx.x;

    // Unroll-by-2 grid-stride: 4 independent 16B streaming loads issued
    // before any dependent gather (MLP_p1 = 4).
    for (; i + stride < nvec; i += 2 * stride) {
        float4 p0 = __ldcs(p4 + i);
        float4 l0 = __ldcs(l4 + i);
        float4 p1 = __ldcs(p4 + i + stride);
        float4 l1 = __ldcs(l4 + i + stride);
        acc += proc4(p0, l0, wg);
        acc += proc4(p1, l1, wg);
    }
    if (i < nvec) {
        float4 p0 = __ldcs(p4 + i);
        float4 l0 = __ldcs(l4 + i);
        acc += proc4(p0, l0, wg);
    }

    // warp reduction
    #pragma unroll
    for (int off = 16; off > 0; off >>= 1)
        acc += __shfl_xor_sync(0xFFFFFFFFu, acc, off);

    __shared__ float warp_part[8];
    int lane = threadIdx.x & 31;
    int wid  = threadIdx.x >> 5;
    if (lane == 0) warp_part[wid] = acc;
    __syncthreads();

    if (wid == 0) {
        float v = (lane < (blockDim.x >> 5)) ? warp_part[lane] : 0.0f;
        #pragma unroll
        for (int off = 4; off > 0; off >>= 1)
            v += __shfl_xor_sync(0xFFFFFFFFu, v, off);

        if (lane == 0) {
            atomicAdd(&g_partial, v);
            __threadfence();
            unsigned int prev = atomicAdd(&g_count, 1u);
            if (prev == gridDim.x - 1) {
                // All other partials are globally visible (their fences
                // precede their counter increments).
                float total = *((volatile float*)&g_partial);
                out[0] = total * inv_count;
                g_partial = 0.0f;        // reset for next graph replay
                g_count   = 0u;
            }
        }
    }
}

extern "C" void kernel_launch(void* const* d_in, const int* in_sizes, int n_in,
                              void* d_out, int out_size) {
    const float* pred = (const float*)d_in[0];
    const float* lab  = (const float*)d_in[1];
    const float* wg   = (const float*)d_in[2];
    float* out = (float*)d_out;

    int total = in_sizes[0];          // B*2 floats
    int nvec  = total / 4;
    float inv_count = 1.0f / (float)total;

    int threads = 256;
    int blocks  = 148 * 8;
    wmse_kernel<<<blocks, threads>>>(pred, lab, wg, out, nvec, inv_count);
}

// round 3
// speedup vs baseline: 1.0881x; 1.0881x over previous
#include <cuda_runtime.h>
#include <cuda_bf16.h>
#include <cstdint>

#define GRID_DIM 201
#define GRID_ELEMS (GRID_DIM * GRID_DIM)   // 40401
#define SMEM_BYTES (GRID_ELEMS * 4)        // 161604

// Self-resetting accumulator state (zero at load; finishing block resets each
// launch so graph replays stay deterministic).
__device__ float        g_partial = 0.0f;
__device__ unsigned int g_count   = 0;

extern __shared__ float s_wg[];

__device__ __forceinline__ float sample_w_smem(float px, float py) {
    // floor((p*180-90)/0.9)+100 == floor(p*200); same for lon with 1.8.
    int xi = __float2int_rd(px * 200.0f);
    int yi = __float2int_rd(py * 200.0f);
    xi = min(max(xi, 0), GRID_DIM - 1);
    yi = min(max(yi, 0), GRID_DIM - 1);
    return s_wg[xi * GRID_DIM + yi];
}

__device__ __forceinline__ float proc4(float4 p, float4 l) {
    float e0 = fabsf(p.x - l.x) + fabsf(p.y - l.y);   // sample 0
    float e1 = fabsf(p.z - l.z) + fabsf(p.w - l.w);   // sample 1
    float w0 = sample_w_smem(p.x, p.y);
    float w1 = sample_w_smem(p.z, p.w);
    // err * (1 + alpha - alpha*w)
    return fmaf(e0, fmaf(-0.1f, w0, 1.1f), e1 * fmaf(-0.1f, w1, 1.1f));
}

__global__ void __launch_bounds__(1024, 1)
wmse_kernel(const float* __restrict__ pred,
            const float* __restrict__ lab,
            const float* __restrict__ wg,
            float* __restrict__ out,
            int nvec,            // float4 chunks (2 samples each)
            float inv_count)     // 1/(B*2)
{
    // ---- cooperative smem fill of the weight grid (vectorized) ----
    {
        const float4* __restrict__ wg4 = reinterpret_cast<const float4*>(wg);
        float4* s4 = reinterpret_cast<float4*>(s_wg);
        for (int j = threadIdx.x; j < GRID_ELEMS / 4; j += blockDim.x)
            s4[j] = __ldg(&wg4[j]);
        if (threadIdx.x == 0)
            s_wg[GRID_ELEMS - 1] = __ldg(&wg[GRID_ELEMS - 1]);
    }
    __syncthreads();

    const float4* __restrict__ p4 = reinterpret_cast<const float4*>(pred);
    const float4* __restrict__ l4 = reinterpret_cast<const float4*>(lab);

    float acc = 0.0f;
    const int stride = gridDim.x * blockDim.x;
    int i = blockIdx.x * blockDim.x + threadIdx.x;

    // Unroll-by-2 grid-stride: 4 independent 16B streaming loads up front.
    for (; i + stride < nvec; i += 2 * stride) {
        float4 p0 = __ldcs(p4 + i);
        float4 l0 = __ldcs(l4 + i);
        float4 p1 = __ldcs(p4 + i + stride);
        float4 l1 = __ldcs(l4 + i + stride);
        acc += proc4(p0, l0);
        acc += proc4(p1, l1);
    }
    if (i < nvec) {
        float4 p0 = __ldcs(p4 + i);
        float4 l0 = __ldcs(l4 + i);
        acc += proc4(p0, l0);
    }

    // ---- reduction ----
    #pragma unroll
    for (int off = 16; off > 0; off >>= 1)
        acc += __shfl_xor_sync(0xFFFFFFFFu, acc, off);

    __shared__ float warp_part[32];
    int lane = threadIdx.x & 31;
    int wid  = threadIdx.x >> 5;
    if (lane == 0) warp_part[wid] = acc;
    __syncthreads();

    if (wid == 0) {
        float v = (lane < (blockDim.x >> 5)) ? warp_part[lane] : 0.0f;
        #pragma unroll
        for (int off = 16; off > 0; off >>= 1)
            v += __shfl_xor_sync(0xFFFFFFFFu, v, off);

        if (lane == 0) {
            atomicAdd(&g_partial, v);
            __threadfence();
            unsigned int prev = atomicAdd(&g_count, 1u);
            if (prev == gridDim.x - 1) {
                float total = *((volatile float*)&g_partial);
                out[0] = total * inv_count;
                g_partial = 0.0f;
                g_count   = 0u;
            }
        }
    }
}

extern "C" void kernel_launch(void* const* d_in, const int* in_sizes, int n_in,
                              void* d_out, int out_size) {
    const float* pred = (const float*)d_in[0];
    const float* lab  = (const float*)d_in[1];
    const float* wg   = (const float*)d_in[2];
    float* out = (float*)d_out;

    int total = in_sizes[0];          // B*2 floats
    int nvec  = total / 4;
    float inv_count = 1.0f / (float)total;

    // One-time (idempotent) opt-in to large dynamic smem; host-side attribute
    // call, not a stream op — legal under graph capture.
    static bool attr_done = false;
    if (!attr_done) {
        cudaFuncSetAttribute(wmse_kernel,
                             cudaFuncAttributeMaxDynamicSharedMemorySize,
                             SMEM_BYTES);
        attr_done = true;
    }

    // One resident CTA per SM.
    int sm_count = 148;
    cudaDeviceGetAttribute(&sm_count, cudaDevAttrMultiProcessorCount, 0);

    wmse_kernel<<<sm_count, 1024, SMEM_BYTES>>>(pred, lab, wg, out,
                                                nvec, inv_count);
}